// round 14
// baseline (speedup 1.0000x reference)
#include <cuda_runtime.h>
#include <cstdint>

#define WARPS_PB   8
#define BLOCK_T    256
#define ROWS_W     32                          // rows per warp-stage chunk
#define F4_W       (ROWS_W * 25)               // 800 float4 per stage
#define CHUNK_B    (F4_W * 16)                 // 12800 bytes
#define STAGES     2
#define SMEM_BYTES (WARPS_PB * STAGES * CHUNK_B)     // 204800 B -> 1 block/SM
#define NBLK       148

// Per-launch control block, zeroed by a cudaMemsetAsync graph node each launch.
struct Ctrl {
    int   flags[20];    // one per producer block (k,i): load-only polling
    int   pad[12];
    float M[200];       // M[k*100 + a]
};
__device__ __align__(16) Ctrl g_ctrl;

__device__ __forceinline__ void mbar_wait(unsigned mbar, unsigned phase) {
    unsigned done;
    asm volatile("{\n\t.reg .pred p;\n\t"
                 "mbarrier.try_wait.parity.acquire.cta.shared::cta.b64 p, [%1], %2;\n\t"
                 "selp.b32 %0, 1, 0, p;\n\t}"
                 : "=r"(done) : "r"(mbar), "r"(phase) : "memory");
    while (!done) {
        asm volatile("{\n\t.reg .pred p;\n\t"
                     "mbarrier.try_wait.parity.acquire.cta.shared::cta.b64 p, [%1], %2, 0x989680;\n\t"
                     "selp.b32 %0, 1, 0, p;\n\t}"
                     : "=r"(done) : "r"(mbar), "r"(phase) : "memory");
    }
}

__global__ void __launch_bounds__(BLOCK_T, 1) fused_kernel(
    const float* __restrict__ x,
    const float* __restrict__ A_real,
    const float* __restrict__ A_imag,
    const float* __restrict__ psi_real,
    const float* __restrict__ psi_imag,
    float2* __restrict__ out,
    int batch, int nchunks)
{
    extern __shared__ __align__(128) float4 sx[];   // [WARPS_PB][STAGES][F4_W]
    __shared__ __align__(16) float sMf[200];
    __shared__ float spr[10], spi[10];
    __shared__ __align__(8) unsigned long long mbar_store[WARPS_PB * STAGES];

    int tid  = threadIdx.x;
    int wid  = tid >> 5;
    int lane = tid & 31;
    int bid  = blockIdx.x;

    unsigned mbar_base = (unsigned)__cvta_generic_to_shared(&mbar_store[0]);
    unsigned wmbar = mbar_base + (wid * STAGES) * 8;
    float4* ws = sx + (size_t)wid * (STAGES * F4_W);

    if (tid < WARPS_PB * STAGES)
        asm volatile("mbarrier.init.shared.b64 [%0], %1;"
                     :: "r"(mbar_base + tid * 8), "r"(1) : "memory");
    if (bid < 20 && tid < 10) { spr[tid] = psi_real[tid]; spi[tid] = psi_imag[tid]; }
    __syncthreads();

    int gwarp  = bid * WARPS_PB + wid;          // static interleave
    int stride = NBLK * WARPS_PB;               // 1184

    // L2 prefetch of a whole chunk: 100 lines of 128B spread across lanes.
    auto prefetchL2 = [&](int chunk) {
        if (chunk < nchunks) {
            const char* base = reinterpret_cast<const char*>(x)
                             + (size_t)chunk * CHUNK_B;
            asm volatile("prefetch.global.L2 [%0];" :: "l"(base + lane * 128));
            asm volatile("prefetch.global.L2 [%0];" :: "l"(base + (32 + lane) * 128));
            asm volatile("prefetch.global.L2 [%0];" :: "l"(base + (64 + lane) * 128));
            if (lane < 4)
                asm volatile("prefetch.global.L2 [%0];" :: "l"(base + (96 + lane) * 128));
        }
    };

    // Issue one 32-row chunk into warp-stage s (single bulk copy, lane 0).
    auto issue = [&](int chunk, int s) {
        if (lane == 0) {
            int rows = batch - chunk * ROWS_W;
            if (rows > ROWS_W) rows = ROWS_W;
            unsigned bytes = (unsigned)rows * 400u;
            unsigned mb = wmbar + s * 8;
            asm volatile("mbarrier.arrive.expect_tx.shared.b64 _, [%0], %1;"
                         :: "r"(mb), "r"(bytes) : "memory");
            unsigned dst = (unsigned)__cvta_generic_to_shared(ws + s * F4_W);
            const float* src = x + (size_t)chunk * (ROWS_W * 100);
            asm volatile("cp.async.bulk.shared::cta.global.mbarrier::complete_tx::bytes "
                         "[%0], [%1], %2, [%3];"
                         :: "r"(dst), "l"(src), "r"(bytes), "r"(mb) : "memory");
        }
    };

    // Prologue: enqueue both smem stages and pre-warm L2 two chunks further.
    if (gwarp < nchunks)          issue(gwarp, 0);
    if (gwarp + stride < nchunks) issue(gwarp + stride, 1);
    prefetchL2(gwarp + 2 * stride);
    prefetchL2(gwarp + 3 * stride);

    // Blocks 0..19: compute the (k,i) partial of M (20 coalesced loads per
    // thread), hidden under the TMA flight. A is read once chip-wide (160KB).
    if (bid < 20) {
        if (tid < 100) {
            int k = bid / 10, i = bid - (bid / 10) * 10;
            int a = tid;
            int base = ((k * 10 + i) * 10) * 100 + a;
            float acc = 0.0f;
            #pragma unroll
            for (int j = 0; j < 10; j++) {
                float wr = spr[i] * spr[j] + spi[i] * spi[j];
                float wi = spr[i] * spi[j] - spi[i] * spr[j];
                acc = fmaf(wr,  __ldg(A_real + base + j * 100), acc);
                acc = fmaf(-wi, __ldg(A_imag + base + j * 100), acc);
            }
            atomicAdd(&g_ctrl.M[k * 100 + a], acc);
            __threadfence();                    // order my adds before the flag
        }
        __syncthreads();
        if (tid == 0) atomicExch(&g_ctrl.flags[bid], 1);
    }

    // All blocks: wait for the 20 producer flags (load-only polling on
    // distinct addresses; shadowed by in-flight TMA copies).
    if (tid < 20) {
        const int* f = &g_ctrl.flags[tid];
        int v;
        do {
            asm volatile("ld.global.cg.b32 %0, [%1];" : "=r"(v) : "l"(f));
            if (!v) __nanosleep(64);
        } while (!v);
    }
    __syncthreads();
    __threadfence();
    if (tid < 200) sMf[tid] = __ldcg(&g_ctrl.M[tid]);   // bypass L1
    __syncthreads();
    const float4* sM4 = reinterpret_cast<const float4*>(sMf);   // [50]

    // Steady loop: warp-private ring; refill-issue also prefetches one
    // warp-iteration ahead so DRAM->L2 runs decoupled from the smem ring.
    int cnt = 0;
    for (int c = gwarp; c < nchunks; c += stride, cnt++) {
        int s = cnt & 1;
        unsigned phase = (cnt >> 1) & 1;
        mbar_wait(wmbar + s * 8, phase);

        int row = c * ROWS_W + lane;
        const float4* xr = ws + s * F4_W + lane * 25;
        float s0 = 0.0f, s1 = 0.0f;
        #pragma unroll
        for (int i = 0; i < 25; i++) {
            float4 v  = xr[i];
            float4 m0 = sM4[i];
            float4 m1 = sM4[25 + i];
            s0 = fmaf(v.x, m0.x, s0); s0 = fmaf(v.y, m0.y, s0);
            s0 = fmaf(v.z, m0.z, s0); s0 = fmaf(v.w, m0.w, s0);
            s1 = fmaf(v.x, m1.x, s1); s1 = fmaf(v.y, m1.y, s1);
            s1 = fmaf(v.z, m1.z, s1); s1 = fmaf(v.w, m1.w, s1);
        }
        if (row < batch) out[row] = make_float2(s0, s1);
        __syncwarp();                      // whole warp done reading stage s

        int cn = c + STAGES * stride;
        if (cn < nchunks) {
            issue(cn, s);
            prefetchL2(cn + stride);       // warm L2 for the next refill
        }
    }
}

extern "C" void kernel_launch(void* const* d_in, const int* in_sizes, int n_in,
                              void* d_out, int out_size) {
    const float* x        = (const float*)d_in[0];  // [BATCH, 100]
    const float* A_real   = (const float*)d_in[1];  // [2,10,10,100]
    const float* A_imag   = (const float*)d_in[2];  // [2,10,10,100]
    const float* psi_real = (const float*)d_in[3];  // [10]
    const float* psi_imag = (const float*)d_in[4];  // [10]

    int batch   = in_sizes[0] / 100;
    int nchunks = (batch + ROWS_W - 1) / ROWS_W;

    static void* ctrl_ptr = nullptr;
    static bool attr_done = false;
    if (!attr_done) {
        cudaFuncSetAttribute(fused_kernel,
                             cudaFuncAttributeMaxDynamicSharedMemorySize, SMEM_BYTES);
        cudaGetSymbolAddress(&ctrl_ptr, g_ctrl);
        attr_done = true;
    }

    // Reset flags + M accumulators each launch (graph-capturable node).
    cudaMemsetAsync(ctrl_ptr, 0, sizeof(Ctrl), 0);

    fused_kernel<<<NBLK, BLOCK_T, SMEM_BYTES>>>(x, A_real, A_imag,
                                                psi_real, psi_imag,
                                                reinterpret_cast<float2*>(d_out),
                                                batch, nchunks);
}